// round 15
// baseline (speedup 1.0000x reference)
#include <cuda_runtime.h>
#include <cstdint>

// v: [8][1024][8][64] f32, w: [1][8][63] f32, out: [8][1024][8][64] f32
// out[n,j,h,d] = A[n,h,a,d] + B[n,h,b,d],  j = a*32+b,  l = c*32+e
//   A = bias @ R,  B = bias @ C
//   R[c,d] = sum_e v[n, c*32+e, h, d],  C[e,d] = sum_c v[n, c*32+e, h, d]
//   bias[h,j,k] = w[h, (32 - k + j) mod 63]
//
// 256 blocks = pair(n,h,q) x row-half G. Each block reads rows
// [G*512, G*512+512) of its 128B column slice ONCE (whole-line LDGs),
// computes R (own 16 c's, complete) + C partials, exchanges 6KB with its
// pair via global L2 + per-pair ticket counter (replay-safe monotonic),
// then matvec + stores its own j-half. 2 blocks/SM -> read/store overlap.

#define THREADS 512

__device__ float4   g_Rh[128][2][128];   // [pair][G][rr*8+d4]
__device__ float4   g_Ch[128][2][256];   // [pair][G][e*8+d4]
__device__ unsigned g_ctr[128];          // per-pair monotonic tickets

__global__ __launch_bounds__(THREADS, 2)
void fused_kernel(const float4* __restrict__ v4,
                  const float*  __restrict__ w,
                  float4* __restrict__ out4) {
    int blk  = blockIdx.x;             // 0..255
    int pair = blk & 127;              // shared (n,h,q) id
    int G    = blk >> 7;               // row-half / j-half owner
    int peer = G ^ 1;
    int q = pair & 1;                  // d-half: float4 cols [q*8, q*8+8)
    int h = (pair >> 1) & 7;
    int n = pair >> 4;                 // 0..7
    int tid = threadIdx.x;

    __shared__ float4 sRp[4][16][8];   // pass-1 partials (eh 0..3)
    __shared__ float4 sCp[2][32][8];   // pass-2 partials (ch 0..1)
    __shared__ float4 sR[32][8], sC[32][8];
    __shared__ float4 sA[32][8], sB[32][8];
    __shared__ float  sb[32][33];

    int d4 = tid & 7;
    const float4* base = v4 + ((size_t)n * 1024) * 128 + h * 16 + q * 8 + d4;

    // ---- Pass 1: R partials for own c = G*16+rr. rows c*32+eh*8+i ----
    {
        int rr = tid >> 5;             // 0..15
        int eh = (tid >> 3) & 3;       // 0..3
        int c = G * 16 + rr;
        const float4* p = base + (size_t)(c * 32 + eh * 8) * 128;
        float4 acc = make_float4(0.f, 0.f, 0.f, 0.f);
        #pragma unroll
        for (int i = 0; i < 8; ++i) {
            float4 x = p[i * 128];
            acc.x += x.x; acc.y += x.y; acc.z += x.z; acc.w += x.w;
        }
        sRp[eh][rr][d4] = acc;
    }

    // ---- Pass 2: C partials over own c's. rows (G*16+ch*8+cc)*32+e (L1 hit) ----
    {
        int e  = tid >> 4;             // 0..31
        int ch = (tid >> 3) & 1;       // 0..1
        const float4* p = base + (size_t)((G * 16 + ch * 8) * 32 + e) * 128;
        float4 acc = make_float4(0.f, 0.f, 0.f, 0.f);
        #pragma unroll
        for (int cc = 0; cc < 8; ++cc) {
            float4 x = p[cc * 32 * 128];
            acc.x += x.x; acc.y += x.y; acc.z += x.z; acc.w += x.w;
        }
        sCp[ch][e][d4] = acc;
    }

    // ---- bias tile ----
    #pragma unroll
    for (int idx = tid; idx < 1024; idx += THREADS) {
        int j = idx >> 5, k = idx & 31;
        sb[j][k] = w[h * 63 + ((32 - k + j) % 63)];
    }
    __syncthreads();

    // ---- combine partials; publish own halves to global ----
    if (tid < 128) {                   // R: 16 x 8 slots
        int rr = tid >> 3;
        float4 a = sRp[0][rr][d4], b = sRp[1][rr][d4];
        float4 c2 = sRp[2][rr][d4], e2 = sRp[3][rr][d4];
        a.x = (a.x + b.x) + (c2.x + e2.x);
        a.y = (a.y + b.y) + (c2.y + e2.y);
        a.z = (a.z + b.z) + (c2.z + e2.z);
        a.w = (a.w + b.w) + (c2.w + e2.w);
        sR[G * 16 + rr][d4] = a;
        g_Rh[pair][G][rr * 8 + d4] = a;
    } else if (tid < 384) {            // C: 32 x 8 slots
        int t = tid - 128;
        int e = t >> 3;
        float4 a = sCp[0][e][d4], b = sCp[1][e][d4];
        a.x += b.x; a.y += b.y; a.z += b.z; a.w += b.w;
        sCp[0][e][d4] = a;             // own half sum kept locally
        g_Ch[pair][G][e * 8 + d4] = a;
    }

    // ---- pairwise ticket exchange (release/acquire via L2) ----
    __threadfence();
    __syncthreads();
    if (tid == 0) {
        unsigned my = atomicAdd(&g_ctr[pair], 1u) + 1u;
        unsigned target = ((my - 1u) / 2u + 1u) * 2u;
        while (*(volatile unsigned*)&g_ctr[pair] < target)
            __nanosleep(32);
    }
    __syncthreads();
    __threadfence();

    // ---- pull peer partials ----
    if (tid < 128) {
        int rr = tid >> 3;
        sR[peer * 16 + rr][d4] = g_Rh[pair][peer][rr * 8 + d4];
    } else if (tid < 384) {
        int t = tid - 128;
        int e = t >> 3;
        float4 mine = sCp[0][e][d4];
        float4 theirs = g_Ch[pair][peer][e * 8 + d4];
        mine.x += theirs.x; mine.y += theirs.y;
        mine.z += theirs.z; mine.w += theirs.w;
        sC[e][d4] = mine;
    }
    __syncthreads();

    // ---- matvec: A = bias@R (tids 0..255), B = bias@C (tids 256..511) ----
    {
        int which = tid >> 8;
        int t = tid & 255;
        int a = t >> 3, dd = t & 7;
        const float4 (*src)[8] = which ? sC : sR;
        float4 acc = make_float4(0.f, 0.f, 0.f, 0.f);
        #pragma unroll
        for (int k = 0; k < 32; ++k) {
            float f = sb[a][k];
            float4 x = src[k][dd];
            acc.x = fmaf(f, x.x, acc.x);
            acc.y = fmaf(f, x.y, acc.y);
            acc.z = fmaf(f, x.z, acc.z);
            acc.w = fmaf(f, x.w, acc.w);
        }
        (which ? sB : sA)[a][dd] = acc;
    }
    __syncthreads();

    // ---- store own j-half: j = G*512 + i*64 + jg  (b = jg&31 invariant) ----
    {
        int jg = tid >> 3;             // 0..63
        float4 y = sB[jg & 31][d4];
        float4* po = out4 + ((size_t)(n * 1024 + G * 512)) * 128
                          + h * 16 + q * 8 + d4;
        #pragma unroll
        for (int i = 0; i < 8; ++i) {
            int jl = i * 64 + jg;              // 0..511
            float4 x = sA[G * 16 + (jl >> 5)][d4];
            x.x += y.x; x.y += y.y; x.z += y.z; x.w += y.w;
            __stcs(po + (size_t)jl * 128, x);
        }
    }
}

extern "C" void kernel_launch(void* const* d_in, const int* in_sizes, int n_in,
                              void* d_out, int out_size) {
    const float* v = (const float*)d_in[0];
    const float* w = (const float*)d_in[1];
    if (n_in >= 2 && in_sizes[0] < in_sizes[1]) {
        const float* tmp = v; v = w; w = tmp;
    }

    fused_kernel<<<256, THREADS>>>((const float4*)v, w, (float4*)d_out);
}

// round 16
// speedup vs baseline: 1.3410x; 1.3410x over previous
#include <cuda_runtime.h>
#include <cstdint>

// v: [8][1024][8][64] f32, w: [1][8][63] f32, out: [8][1024][8][64] f32
// out[n,j,h,d] = A[n,h,a,d] + B[n,h,b,d],  j = a*32+b,  l = c*32+e
//   A = bias @ R,  B = bias @ C
//   R[c,d] = sum_e v[n, c*32+e, h, d],  C[e,d] = sum_c v[n, c*32+e, h, d]
//   bias[h,j,k] = w[h, (32 - k + j) mod 63]
//
// R14 skeleton + 256-bit loads: 128 blocks = (n,h,d-half), 512 threads.
// Thread (c, eh, d8) loads one 32B sector per LDG (ld.global.nc.v8.b32,
// L2::evict_last): warp covers 8 whole 128B lines per instruction, half the
// request count of the float4 version. 8-deep chains both passes.

#define THREADS 512

struct f8 { float4 lo, hi; };

__device__ __forceinline__ f8 ldg256(const void* p) {
    f8 v;
    asm volatile(
        "ld.global.nc.L2::evict_last.v8.f32 {%0,%1,%2,%3,%4,%5,%6,%7}, [%8];"
        : "=f"(v.lo.x), "=f"(v.lo.y), "=f"(v.lo.z), "=f"(v.lo.w),
          "=f"(v.hi.x), "=f"(v.hi.y), "=f"(v.hi.z), "=f"(v.hi.w)
        : "l"(p));
    return v;
}

__global__ __launch_bounds__(THREADS, 1)
void fused_kernel(const float4* __restrict__ v4,
                  const float*  __restrict__ w,
                  float4* __restrict__ out4) {
    int blk = blockIdx.x;          // 0..127
    int q = blk & 1;               // d-half: float4 cols [q*8, q*8+8)
    int h = (blk >> 1) & 7;
    int n = blk >> 4;              // 0..7
    int tid = threadIdx.x;

    __shared__ float4 sRp[4][32][8];   // pass-1 partials (eh 0..3)
    __shared__ float4 sCp[4][32][8];   // pass-2 partials
    __shared__ float4 sR[32][8], sC[32][8];
    __shared__ float4 sA[32][8], sB[32][8];
    __shared__ float  sb[32][33];

    int c  = tid >> 4;        // 0..31 : c (pass1) / e (pass2)
    int eh = (tid >> 2) & 3;  // 0..3  : 8-row sub-group
    int d8 = tid & 3;         // 0..3  : 32B sector within the 128B row slice

    // byte base of this thread's sector within row 0 of the slice
    const char* basec = (const char*)(v4 + ((size_t)n * 1024) * 128 + h * 16 + q * 8)
                        + d8 * 32;

    // ---- Pass 1: R partials. rows l = c*32 + eh*8 + i (contiguous lines) ----
    {
        const char* p = basec + (size_t)(c * 32 + eh * 8) * 2048;   // 128 f4 = 2048B/row
        float4 aLo = make_float4(0.f, 0.f, 0.f, 0.f);
        float4 aHi = make_float4(0.f, 0.f, 0.f, 0.f);
        #pragma unroll
        for (int i = 0; i < 8; ++i) {
            f8 x = ldg256(p + (size_t)i * 2048);
            aLo.x += x.lo.x; aLo.y += x.lo.y; aLo.z += x.lo.z; aLo.w += x.lo.w;
            aHi.x += x.hi.x; aHi.y += x.hi.y; aHi.z += x.hi.z; aHi.w += x.hi.w;
        }
        sRp[eh][c][d8 * 2]     = aLo;
        sRp[eh][c][d8 * 2 + 1] = aHi;
    }

    // ---- Pass 2: C partials. rows l = (eh*8+i)*32 + c (L1 re-hit) ----
    {
        const char* p = basec + (size_t)(eh * 8 * 32 + c) * 2048;
        float4 aLo = make_float4(0.f, 0.f, 0.f, 0.f);
        float4 aHi = make_float4(0.f, 0.f, 0.f, 0.f);
        #pragma unroll
        for (int i = 0; i < 8; ++i) {
            f8 x = ldg256(p + (size_t)i * 32 * 2048);
            aLo.x += x.lo.x; aLo.y += x.lo.y; aLo.z += x.lo.z; aLo.w += x.lo.w;
            aHi.x += x.hi.x; aHi.y += x.hi.y; aHi.z += x.hi.z; aHi.w += x.hi.w;
        }
        sCp[eh][c][d8 * 2]     = aLo;
        sCp[eh][c][d8 * 2 + 1] = aHi;
    }

    // ---- bias tile (2 entries/thread) ----
    #pragma unroll
    for (int idx = tid; idx < 1024; idx += THREADS) {
        int j = idx >> 5, k = idx & 31;
        sb[j][k] = w[h * 63 + ((32 - k + j) % 63)];
    }
    __syncthreads();

    // ---- combine 4-way partials (512 threads: R half, C half) ----
    {
        int which = tid >> 8;          // 0: R, 1: C
        int t = tid & 255;
        int kk = t >> 3, dd = t & 7;
        const float4 (*p)[32][8] = which ? sCp : sRp;
        float4 a = p[0][kk][dd], b = p[1][kk][dd];
        float4 c2 = p[2][kk][dd], e2 = p[3][kk][dd];
        a.x = (a.x + b.x) + (c2.x + e2.x);
        a.y = (a.y + b.y) + (c2.y + e2.y);
        a.z = (a.z + b.z) + (c2.z + e2.z);
        a.w = (a.w + b.w) + (c2.w + e2.w);
        (which ? sC : sR)[kk][dd] = a;
    }
    __syncthreads();

    // ---- matvec: A = bias@R (tids 0..255), B = bias@C (tids 256..511) ----
    {
        int which = tid >> 8;
        int t = tid & 255;
        int a = t >> 3, dd = t & 7;
        const float4 (*src)[8] = which ? sC : sR;
        float4 acc = make_float4(0.f, 0.f, 0.f, 0.f);
        #pragma unroll
        for (int k = 0; k < 32; ++k) {
            float f = sb[a][k];
            float4 x = src[k][dd];
            acc.x = fmaf(f, x.x, acc.x);
            acc.y = fmaf(f, x.y, acc.y);
            acc.z = fmaf(f, x.z, acc.z);
            acc.w = fmaf(f, x.w, acc.w);
        }
        (which ? sB : sA)[a][dd] = acc;
    }
    __syncthreads();

    // ---- store: j = i*64 + jg; streaming (evict-first) ----
    {
        int jg = tid >> 3;             // 0..63
        int d4 = tid & 7;
        float4* po = out4 + ((size_t)n * 1024) * 128 + h * 16 + q * 8 + d4;
        #pragma unroll
        for (int i = 0; i < 16; ++i) {
            int j = i * 64 + jg;
            int a = j >> 5, b = j & 31;
            float4 x = sA[a][d4];
            float4 y = sB[b][d4];
            x.x += y.x; x.y += y.y; x.z += y.z; x.w += y.w;
            __stcs(po + (size_t)j * 128, x);
        }
    }
}

extern "C" void kernel_launch(void* const* d_in, const int* in_sizes, int n_in,
                              void* d_out, int out_size) {
    const float* v = (const float*)d_in[0];
    const float* w = (const float*)d_in[1];
    if (n_in >= 2 && in_sizes[0] < in_sizes[1]) {
        const float* tmp = v; v = w; w = tmp;
    }

    fused_kernel<<<128, THREADS>>>((const float4*)v, w, (float4*)d_out);
}

// round 17
// speedup vs baseline: 1.3528x; 1.0087x over previous
#include <cuda_runtime.h>
#include <cstdint>

// v: [8][1024][8][64] f32, w: [1][8][63] f32, out: [8][1024][8][64] f32
// out[n,j,h,d] = A[n,h,a,d] + B[n,h,b,d],  j = a*32+b,  l = c*32+e
//   A = bias @ R,  B = bias @ C
//   R[c,d] = sum_e v[n, c*32+e, h, d],  C[e,d] = sum_c v[n, c*32+e, h, d]
//   bias[h,j,k] = w[h, (32 - k + j) mod 63]
//
// FINAL: best-measured skeleton (10.72us). 128 blocks = (n, h, d-half),
// 512 threads, 1 block/SM. Pass1 R (contiguous rows, DRAM), pass2 C
// (stride-32, L1 re-hit), tiny smem matvec, coalesced streaming stores.
// Launch overhead (~4-5us/graph node) + 32MB mandatory DRAM ~= the floor;
// 8 structural variants (occupancy/MLP/cp.async/clusters/grid-barrier/
// pair-exchange/L2-policy/256b-loads) all measured 10.7-15us.

#define THREADS 512

__device__ __forceinline__ uint64_t mk_evict_last_policy() {
    uint64_t pol;
    asm volatile("createpolicy.fractional.L2::evict_last.b64 %0, 1.0;" : "=l"(pol));
    return pol;
}

__device__ __forceinline__ float4 ldg_keep(const float4* p, uint64_t pol) {
    float4 v;
    asm volatile("ld.global.nc.L2::cache_hint.v4.f32 {%0,%1,%2,%3}, [%4], %5;"
                 : "=f"(v.x), "=f"(v.y), "=f"(v.z), "=f"(v.w)
                 : "l"(p), "l"(pol));
    return v;
}

__global__ __launch_bounds__(THREADS, 1)
void fused_kernel(const float4* __restrict__ v4,
                  const float*  __restrict__ w,
                  float4* __restrict__ out4) {
    int blk = blockIdx.x;          // 0..127
    int q = blk & 1;               // d-half: float4 cols [q*8, q*8+8)
    int h = (blk >> 1) & 7;
    int n = blk >> 4;              // 0..7
    int tid = threadIdx.x;

    __shared__ float4 sRp[2][32][8];   // pass-1 partials (eh split)
    __shared__ float4 sCp[2][32][8];
    __shared__ float4 sR[32][8], sC[32][8];
    __shared__ float4 sA[32][8], sB[32][8];
    __shared__ float  sb[32][33];

    int c  = tid >> 4;        // 0..31 : c (pass1) / e (pass2)
    int eh = (tid >> 3) & 1;  // 0..1  : row sub-group
    int d4 = tid & 7;         // 0..7  : float4 column within the half

    uint64_t pol = mk_evict_last_policy();
    const float4* base = v4 + ((size_t)n * 1024) * 128 + h * 16 + q * 8 + d4;

    // ---- Pass 1: R partials. rows l = c*32 + eh*16 + i (contiguous) ----
    {
        const float4* p = base + (size_t)(c * 32 + eh * 16) * 128;
        float4 acc = make_float4(0.f, 0.f, 0.f, 0.f);
        #pragma unroll
        for (int i = 0; i < 16; ++i) {
            float4 x = ldg_keep(p + i * 128, pol);
            acc.x += x.x; acc.y += x.y; acc.z += x.z; acc.w += x.w;
        }
        sRp[eh][c][d4] = acc;
    }

    // ---- Pass 2: C partials. rows l = (eh*16+i)*32 + c (L1 re-hit) ----
    {
        const float4* p = base + (size_t)(eh * 16 * 32 + c) * 128;
        float4 acc = make_float4(0.f, 0.f, 0.f, 0.f);
        #pragma unroll
        for (int i = 0; i < 16; ++i) {
            float4 x = ldg_keep(p + i * 32 * 128, pol);
            acc.x += x.x; acc.y += x.y; acc.z += x.z; acc.w += x.w;
        }
        sCp[eh][c][d4] = acc;
    }

    // ---- bias tile (2 entries/thread, branch-free mod 63) ----
    #pragma unroll
    for (int idx = tid; idx < 1024; idx += THREADS) {
        int j = idx >> 5, k = idx & 31;
        int t = 32 - k + j;                // 1..63 or 0..63 range: [1,63]
        t = (t >= 63) ? t - 63 : t;        // mod 63 without division
        sb[j][k] = w[h * 63 + t];
    }
    __syncthreads();

    // ---- combine eh-partials (512 threads: R half, C half) ----
    {
        int which = tid >> 8;          // 0: R, 1: C
        int t = tid & 255;
        int kk = t >> 3, dd = t & 7;
        const float4 (*p)[32][8] = which ? sCp : sRp;
        float4 a = p[0][kk][dd], b = p[1][kk][dd];
        a.x += b.x; a.y += b.y; a.z += b.z; a.w += b.w;
        (which ? sC : sR)[kk][dd] = a;
    }
    __syncthreads();

    // ---- matvec: A = bias@R (tids 0..255), B = bias@C (tids 256..511) ----
    {
        int which = tid >> 8;
        int t = tid & 255;
        int a = t >> 3, dd = t & 7;
        const float4 (*src)[8] = which ? sC : sR;
        float4 acc = make_float4(0.f, 0.f, 0.f, 0.f);
        #pragma unroll
        for (int k = 0; k < 32; ++k) {
            float f = sb[a][k];
            float4 x = src[k][dd];
            acc.x = fmaf(f, x.x, acc.x);
            acc.y = fmaf(f, x.y, acc.y);
            acc.z = fmaf(f, x.z, acc.z);
            acc.w = fmaf(f, x.w, acc.w);
        }
        (which ? sB : sA)[a][dd] = acc;
    }
    __syncthreads();

    // ---- store: j = i*64 + jg. b = jg&31 is loop-invariant -> hoist sB ----
    {
        int jg = tid >> 3;             // 0..63
        float4 y = sB[jg & 31][d4];    // invariant across i
        int a0 = jg >> 5;              // 0..1
        float4* po = out4 + ((size_t)n * 1024 + jg) * 128 + h * 16 + q * 8 + d4;
        #pragma unroll
        for (int i = 0; i < 16; ++i) {
            float4 x = sA[i * 2 + a0][d4];
            x.x += y.x; x.y += y.y; x.z += y.z; x.w += y.w;
            __stcs(po + (size_t)i * 64 * 128, x);
        }
    }
}

extern "C" void kernel_launch(void* const* d_in, const int* in_sizes, int n_in,
                              void* d_out, int out_size) {
    const float* v = (const float*)d_in[0];
    const float* w = (const float*)d_in[1];
    if (n_in >= 2 && in_sizes[0] < in_sizes[1]) {
        const float* tmp = v; v = w; w = tmp;
    }

    fused_kernel<<<128, THREADS>>>((const float4*)v, w, (float4*)d_out);
}